// round 12
// baseline (speedup 1.0000x reference)
#include <cuda_runtime.h>
#include <math.h>

#define NB   16
#define NCI  512
#define NCO  128
#define LAMBDA 0.2f
#define INV_SQRT2PI 0.39894228040143267794f
// -0.5 * log2(e)
#define NEG_HALF_LOG2E -0.72134752044448170367f
#define PADV 68
#define PADT 64

__device__ float g_logits[NB * NCO];
__device__ unsigned g_ctr = 0;

typedef unsigned long long u64;
union F4 { float4 f; u64 d[2]; float s[4]; };

__device__ __forceinline__ u64 pk2(float lo, float hi) {
    u64 r; asm("mov.b64 %0,{%1,%2};" : "=l"(r) : "f"(lo), "f"(hi)); return r;
}
__device__ __forceinline__ void up2(u64 v, float& lo, float& hi) {
    asm("mov.b64 {%0,%1},%2;" : "=f"(lo), "=f"(hi) : "l"(v));
}
__device__ __forceinline__ u64 fma2(u64 a, u64 b, u64 c) {
    u64 d; asm("fma.rn.f32x2 %0,%1,%2,%3;" : "=l"(d) : "l"(a), "l"(b), "l"(c)); return d;
}
__device__ __forceinline__ u64 mul2(u64 a, u64 b) {
    u64 d; asm("mul.rn.f32x2 %0,%1,%2;" : "=l"(d) : "l"(a), "l"(b)); return d;
}
__device__ __forceinline__ u64 add2(u64 a, u64 b) {
    u64 d; asm("add.rn.f32x2 %0,%1,%2;" : "=l"(d) : "l"(a), "l"(b)); return d;
}
__device__ __forceinline__ void cp16(void* smem, const void* g) {
    unsigned s = (unsigned)__cvta_generic_to_shared(smem);
    asm volatile("cp.async.cg.shared.global [%0], [%1], 16;" :: "r"(s), "l"(g));
}
__device__ __forceinline__ unsigned smem_u32(const void* p) {
    return (unsigned)__cvta_generic_to_shared(p);
}
__device__ __forceinline__ unsigned mapa_u32(unsigned addr, unsigned rank) {
    unsigned r;
    asm("mapa.shared::cluster.u32 %0, %1, %2;" : "=r"(r) : "r"(addr), "r"(rank));
    return r;
}
__device__ __forceinline__ void st_cluster_f32(unsigned addr, float v) {
    asm volatile("st.shared::cluster.f32 [%0], %1;" :: "r"(addr), "f"(v) : "memory");
}
__device__ __forceinline__ void cluster_sync_() {
    asm volatile("barrier.cluster.arrive.aligned;" ::: "memory");
    asm volatile("barrier.cluster.wait.aligned;" ::: "memory");
}

// ---------------------------------------------------------------------------
// Cluster-split fused EM routing: 2-CTA cluster shares one (b,co); rank r
// owns ci in [r*256, (r+1)*256). Exchange buffers xS1/xS2/misc are DEDICATED
// (no aliasing with mus/Aa/Cc/nm -- the R11 NaN bug). Sp slabs + pw reuse the
// dead pose/trans staging area after V-gen (Sp1+Sp2 fit inside Pb0, whose
// last read is at k=6, disjoint from k=7's Pb1/Tb1 reads).
// ---------------------------------------------------------------------------
__global__ void __launch_bounds__(512, 2) __cluster_dims__(2, 1, 1)
k_fused(const float* __restrict__ act, const float* __restrict__ pose,
        const float* __restrict__ trans, const float* __restrict__ ba,
        const float* __restrict__ bb, float* __restrict__ out)
{
    extern __shared__ float sh[];
    float* Pb0  = sh;                    // 32*68 = 2176
    float* Pb1  = Pb0 + 32 * PADV;       // 2176
    float* Tb0  = Pb1 + 32 * PADV;       // 32*64 = 2048
    float* Tb1  = Tb0 + 32 * PADT;       // 2048
    float* Sp1  = sh;                    // alias (dead staging): [16*64]
    float* Sp2  = sh + 1024;             // alias: [16*64] (within Pb0)
    float* pw   = sh;                    // alias: [2*256] e-step partials
    float* Vs   = Tb1 + 32 * PADT;       // 256*68
    float* rw   = Vs + 256 * PADV;       // [256]
    float* acts = rw + 256;              // [256]
    float* mus  = acts + 256;            // [64]  dedicated
    float* nm   = mus + 64;              // [64]  dedicated
    float* Aa   = nm + 64;               // [64]  dedicated
    float* Cc   = Aa + 64;               // [64]  dedicated
    float* xS1  = Cc + 64;               // [2][64] exchange (dedicated)
    float* xS2  = xS1 + 128;             // [2][64] exchange (dedicated)
    float* misc = xS2 + 128;             // [16]: 0..7 wslab, 8 lsum, 9 flag, 10..11 xW

    const unsigned rank = blockIdx.x;    // == cluster_ctarank (cluster (2,1,1))
    const int co = blockIdx.y, b = blockIdx.z;
    const int t = threadIdx.x, lane = t & 31, wid = t >> 5;
    const int tq = t & 15, trow = t >> 4;
    const int q = tq >> 1, s4 = (tq & 1) << 2;

    auto stage = [&](int s, int bs) {
        const int row = trow, f4 = tq << 2;
        const int gci = (int)rank * 256 + s * 32 + row;
        cp16((bs ? Pb1 : Pb0) + row * PADV + f4,
             pose + ((size_t)(b * NCI + gci)) * 64 + f4);
        cp16((bs ? Tb1 : Tb0) + row * PADT + f4,
             trans + ((size_t)(gci * NCO + co)) * 64 + f4);
        asm volatile("cp.async.commit_group;" ::: "memory");
    };

    // ---- init + asum exchange ----
    float a = 0.f;
    if (t < 256) { a = act[b * NCI + (int)rank * 256 + t]; acts[t] = a; }
    if (t < 16) misc[t] = 0.f;
    stage(0, 0);
    __syncthreads();
    if (t < 256) {
        float s = a;
        #pragma unroll
        for (int o = 16; o; o >>= 1) s += __shfl_xor_sync(0xffffffffu, s, o);
        if (lane == 0) misc[wid] = s;
    }
    __syncthreads();
    if (t == 0) {
        float sl = misc[0] + misc[1] + misc[2] + misc[3]
                 + misc[4] + misc[5] + misc[6] + misc[7];
        float* p = &misc[10 + rank];
        *p = sl;
        st_cluster_f32(mapa_u32(smem_u32(p), rank ^ 1u), sl);
    }
    cluster_sync_();
    {   // read right after sync; next writer gated by 2 later cluster syncs
        const float asum = misc[10] + misc[11];
        if (t < 256) rw[t] = acts[t] / asum;
    }

    // ---- V generation (packed fma2) + fused m1 stats ----
    float v8[8];
    u64 s1a = 0ull, s1b = 0ull, s2a = 0ull, s2b = 0ull;
    for (int k = 0; k < 8; k++) {
        asm volatile("cp.async.wait_group 0;" ::: "memory");
        __syncthreads();
        if (k < 7) stage(k + 1, (k + 1) & 1);
        const float* pr = ((k & 1) ? Pb1 : Pb0) + trow * PADV;
        const float* tr = ((k & 1) ? Tb1 : Tb0) + trow * PADT;
        const int lci = k * 32 + trow;
        u64 a01 = 0ull, a23 = 0ull;
        #pragma unroll
        for (int p = 0; p < 8; p++) {
            const float pv = pr[p * 8 + q];
            const u64 pv2 = pk2(pv, pv);
            F4 tv; tv.f = *(const float4*)(tr + p * 8 + s4);
            a01 = fma2(pv2, tv.d[0], a01);
            a23 = fma2(pv2, tv.d[1], a23);
        }
        F4 vv; vv.d[0] = a01; vv.d[1] = a23;
        *(float4*)(Vs + lci * PADV + tq * 4) = vv.f;
        const float r = rw[lci];
        const u64 r2 = pk2(r, r);
        const u64 rv0 = mul2(r2, a01), rv1 = mul2(r2, a23);
        s1a = add2(s1a, rv0); s1b = add2(s1b, rv1);
        s2a = fma2(rv0, a01, s2a); s2b = fma2(rv1, a23, s2b);
    }
    up2(s1a, v8[0], v8[1]); up2(s1b, v8[2], v8[3]);
    up2(s2a, v8[4], v8[5]); up2(s2b, v8[6], v8[7]);

    // ---- cluster stats reduce: slabs -> 64-thread sum -> push-exchange ----
    // m0 (M0_EXPR) reads dedicated mus[] BEFORE it is overwritten (same thread).
    #define REDUCE_STATS(INVW_EXPR, M0_EXPR, FINAL)                             \
    {                                                                           \
        _Pragma("unroll")                                                       \
        for (int j = 0; j < 8; j++)                                             \
            v8[j] += __shfl_xor_sync(0xffffffffu, v8[j], 16);                   \
        if (lane < 16) {                                                        \
            *(float4*)(Sp1 + wid * 64 + lane * 4) =                             \
                make_float4(v8[0], v8[1], v8[2], v8[3]);                        \
            *(float4*)(Sp2 + wid * 64 + lane * 4) =                             \
                make_float4(v8[4], v8[5], v8[6], v8[7]);                        \
        }                                                                       \
        __syncthreads();                                                        \
        if (t < 64) {                                                           \
            float s1 = 0.f, s2 = 0.f;                                           \
            _Pragma("unroll")                                                   \
            for (int ww = 0; ww < 16; ww++) {                                   \
                s1 += Sp1[ww * 64 + t];                                         \
                s2 += Sp2[ww * 64 + t];                                         \
            }                                                                   \
            float* p1 = xS1 + rank * 64 + t;                                    \
            float* p2 = xS2 + rank * 64 + t;                                    \
            *p1 = s1; *p2 = s2;                                                 \
            st_cluster_f32(mapa_u32(smem_u32(p1), rank ^ 1u), s1);              \
            st_cluster_f32(mapa_u32(smem_u32(p2), rank ^ 1u), s2);              \
        }                                                                       \
        cluster_sync_();                                                        \
        if (t < 64) {                                                           \
            const float s1 = xS1[t] + xS1[64 + t];   /* same slot order in  */  \
            const float s2 = xS2[t] + xS2[64 + t];   /* both CTAs -> equal  */  \
            const float invW = (INVW_EXPR);                                     \
            const float m0 = (M0_EXPR);                                         \
            const float dd = s1 * invW;                                         \
            const float mu = m0 + dd;                                           \
            const float var = fmaxf(s2 * invW - dd * dd, 1e-30f);               \
            mus[t] = mu;                                                        \
            nm[t] = -mu;                                                        \
            Aa[t] = NEG_HALF_LOG2E / var;                                       \
            Cc[t] = INV_SQRT2PI * rsqrtf(var);                                  \
            if (FINAL) {                                                        \
                if (rank == 0)                                                  \
                    out[NB * NCO + ((size_t)(b * NCO + co)) * 64 + t] = mu;     \
                float l = 0.5f * logf(var);                                     \
                _Pragma("unroll")                                               \
                for (int o = 16; o; o >>= 1)                                    \
                    l += __shfl_xor_sync(0xffffffffu, l, o);                    \
                if (lane == 0) atomicAdd(&misc[8], l);                          \
            }                                                                   \
        }                                                                       \
        __syncthreads();                                                        \
    }

    // ---- e-step: (ci, qs-half) per thread; W pushed + exchanged ----
    #define E_STEP(WTOT_VAR)                                                    \
    float WTOT_VAR;                                                             \
    {                                                                           \
        const int cie = t & 255, half = t >> 8;                                 \
        const float* Vb = Vs + cie * PADV + half * 32;                          \
        const int cb = half * 32;                                               \
        float acc = 0.f;                                                        \
        _Pragma("unroll 4")                                                     \
        for (int j = 0; j < 8; j++) {                                           \
            F4 v;  v.f  = *(const float4*)(Vb + j * 4);                         \
            F4 nv; nv.f = *(const float4*)(nm + cb + j * 4);                    \
            F4 Av; Av.f = *(const float4*)(Aa + cb + j * 4);                    \
            F4 Cv; Cv.f = *(const float4*)(Cc + cb + j * 4);                    \
            const u64 d0 = add2(v.d[0], nv.d[0]);                               \
            const u64 d1 = add2(v.d[1], nv.d[1]);                               \
            const u64 e0 = mul2(Av.d[0], mul2(d0, d0));                         \
            const u64 e1 = mul2(Av.d[1], mul2(d1, d1));                         \
            float a0, a1, a2, a3; up2(e0, a0, a1); up2(e1, a2, a3);             \
            acc = fmaf(Cv.s[0], exp2f(a0), acc);                                \
            acc = fmaf(Cv.s[1], exp2f(a1), acc);                                \
            acc = fmaf(Cv.s[2], exp2f(a2), acc);                                \
            acc = fmaf(Cv.s[3], exp2f(a3), acc);                                \
        }                                                                       \
        pw[half * 256 + cie] = acc;                                             \
        __syncthreads();                                                        \
        if (t < 256) {                                                          \
            const float w = acts[t] * (pw[t] + pw[256 + t]);                    \
            rw[t] = w;                                                          \
            float ws = w;                                                       \
            _Pragma("unroll")                                                   \
            for (int o = 16; o; o >>= 1)                                        \
                ws += __shfl_xor_sync(0xffffffffu, ws, o);                      \
            if (lane == 0) misc[wid] = ws;                                      \
        }                                                                       \
        __syncthreads();                                                        \
        if (t == 0) {                                                           \
            float W = misc[0] + misc[1] + misc[2] + misc[3]                     \
                    + misc[4] + misc[5] + misc[6] + misc[7];                    \
            float* p = &misc[10 + rank];                                        \
            *p = W;                                                             \
            st_cluster_f32(mapa_u32(smem_u32(p), rank ^ 1u), W);                \
        }                                                                       \
        cluster_sync_();                                                        \
        WTOT_VAR = misc[10] + misc[11];                                         \
    }

    // ---- m-step: shifted variance around previous mu (read from mus) ----
    #define M_STEP()                                                            \
    {                                                                           \
        const float4 m0v = *(const float4*)(mus + tq * 4);                      \
        const u64 nm0 = pk2(-m0v.x, -m0v.y), nm1 = pk2(-m0v.z, -m0v.w);         \
        s1a = 0ull; s1b = 0ull; s2a = 0ull; s2b = 0ull;                         \
        _Pragma("unroll 4")                                                     \
        for (int i = 0; i < 8; i++) {                                           \
            const int lci = i * 32 + trow;                                      \
            const float r = rw[lci];                                            \
            F4 v; v.f = *(const float4*)(Vs + lci * PADV + tq * 4);             \
            const u64 vs0 = add2(v.d[0], nm0), vs1 = add2(v.d[1], nm1);         \
            const u64 r2 = pk2(r, r);                                           \
            const u64 rv0 = mul2(r2, vs0), rv1 = mul2(r2, vs1);                 \
            s1a = add2(s1a, rv0); s1b = add2(s1b, rv1);                         \
            s2a = fma2(rv0, vs0, s2a); s2b = fma2(rv1, vs1, s2b);               \
        }                                                                       \
        up2(s1a, v8[0], v8[1]); up2(s1b, v8[2], v8[3]);                         \
        up2(s2a, v8[4], v8[5]); up2(s2b, v8[6], v8[7]);                         \
    }

    REDUCE_STATS(1.f, 0.f, 0)                 // m1 (weights pre-normalized)
    E_STEP(W1)                                // e1
    M_STEP()
    REDUCE_STATS(1.f / W1, mus[t], 0)         // m2 (shifted variance)
    E_STEP(W2)                                // e2
    M_STEP()
    REDUCE_STATS(1.f / W2, mus[t], 1)         // m3 -> mu out + logit sum

    if (rank == 0) {
        if (t == 0) {
            g_logits[b * NCO + co] =
                LAMBDA * (ba[co] - bb[co] - misc[8]);
            __threadfence();
            unsigned done = atomicAdd(&g_ctr, 1u);
            misc[9] = (done == (unsigned)(NB * NCO - 1)) ? 1.f : 0.f;
        }
        __syncthreads();
        if (misc[9] != 0.f) {
            // last rank-0 block: softmax over co for all 16 batch rows.
            __threadfence();
            float x0 = g_logits[wid * NCO + lane * 4 + 0];
            float x1 = g_logits[wid * NCO + lane * 4 + 1];
            float x2 = g_logits[wid * NCO + lane * 4 + 2];
            float x3 = g_logits[wid * NCO + lane * 4 + 3];
            float m = fmaxf(fmaxf(x0, x1), fmaxf(x2, x3));
            #pragma unroll
            for (int o = 16; o; o >>= 1)
                m = fmaxf(m, __shfl_xor_sync(0xffffffffu, m, o));
            const float e0 = __expf(x0 - m), e1 = __expf(x1 - m);
            const float e2 = __expf(x2 - m), e3 = __expf(x3 - m);
            float s = (e0 + e1) + (e2 + e3);
            #pragma unroll
            for (int o = 16; o; o >>= 1)
                s += __shfl_xor_sync(0xffffffffu, s, o);
            const float inv = 1.f / s;
            out[wid * NCO + lane * 4 + 0] = e0 * inv;
            out[wid * NCO + lane * 4 + 1] = e1 * inv;
            out[wid * NCO + lane * 4 + 2] = e2 * inv;
            out[wid * NCO + lane * 4 + 3] = e3 * inv;
            if (t == 0) g_ctr = 0;            // reset for next graph replay
        }
    }
}

// ---------------------------------------------------------------------------
extern "C" void kernel_launch(void* const* d_in, const int* in_sizes, int n_in,
                              void* d_out, int out_size)
{
    const float* act   = (const float*)d_in[0];
    const float* pose  = (const float*)d_in[1];
    const float* trans = (const float*)d_in[2];
    const float* ba    = (const float*)d_in[3];
    const float* bb    = (const float*)d_in[4];
    float* out = (float*)d_out;

    // floats: staging 8448 + Vs 17408 + rw/acts 512 + mus/nm/Aa/Cc 256
    //         + xS1/xS2 256 + misc 16  = 26896  (107,584 B -> 2 CTAs/SM)
    const int smem = (2 * 32 * PADV + 2 * 32 * PADT + 256 * PADV
                      + 512 + 256 + 256 + 16) * (int)sizeof(float);
    cudaFuncSetAttribute(k_fused, cudaFuncAttributeMaxDynamicSharedMemorySize, smem);

    dim3 grid(2, NCO, NB);                 // cluster (2,1,1) over grid.x
    k_fused<<<grid, 512, smem>>>(act, pose, trans, ba, bb, out);
}